// round 10
// baseline (speedup 1.0000x reference)
#include <cuda_runtime.h>
#include <cstdint>

static constexpr int B_  = 16;
static constexpr int H_  = 2048;
static constexpr int I_  = 1024;
static constexpr int NT  = 256;   // 8 warps; each thread owns 8 columns
static constexpr int NS  = 3;     // TMA ring depth (3 x 8 KB)
static constexpr int ROW_BYTES = H_ * 4;   // 8192

__device__ __forceinline__ float flg2(float x){ float r; asm("lg2.approx.f32 %0,%1;" : "=f"(r) : "f"(x)); return r; }
__device__ __forceinline__ float frcp(float x){ float r; asm("rcp.approx.f32 %0,%1;" : "=f"(r) : "f"(x)); return r; }
__device__ __forceinline__ float fex2(float x){ float r; asm("ex2.approx.f32 %0,%1;" : "=f"(r) : "f"(x)); return r; }

__device__ __forceinline__ uint32_t s2u(const void* p){ return (uint32_t)__cvta_generic_to_shared(p); }

__device__ __forceinline__ void mbar_init(uint32_t a, uint32_t cnt){
    asm volatile("mbarrier.init.shared::cta.b64 [%0], %1;" :: "r"(a), "r"(cnt) : "memory");
}
__device__ __forceinline__ void mbar_expect_tx(uint32_t a, uint32_t bytes){
    asm volatile("mbarrier.arrive.expect_tx.shared::cta.b64 _, [%0], %1;" :: "r"(a), "r"(bytes) : "memory");
}
__device__ __forceinline__ void mbar_wait(uint32_t a, uint32_t parity){
    asm volatile(
        "{\n\t.reg .pred P;\n\t"
        "W_%=:\n\t"
        "mbarrier.try_wait.parity.acquire.cta.shared::cta.b64 P, [%0], %1, 0x989680;\n\t"
        "@!P bra W_%=;\n\t}"
        :: "r"(a), "r"(parity) : "memory");
}
__device__ __forceinline__ void bulk_ld(uint32_t dst_smem, const void* src, uint32_t bytes, uint32_t mbar){
    asm volatile("cp.async.bulk.shared::cta.global.mbarrier::complete_tx::bytes [%0], [%1], %2, [%3];"
        :: "r"(dst_smem), "l"(src), "r"(bytes), "r"(mbar) : "memory");
}
__device__ __forceinline__ void fence_async(){
    asm volatile("fence.proxy.async.shared::cta;" ::: "memory");
}

// w = se / (-ln u) = (-se*log2e) * rcp(lg2(u)).
// Clamp lg2(u) <= -4e-8: lg2.approx's 2^-22 abs error can flip sign near u=1;
// the clamped weight is huge -> dominates num AND den -> output -> h of that
// element, the true u->1 limit. u=0 -> lg2=-inf -> rcp=-0 -> w=+0 (negligible).
__device__ __forceinline__ float gwr(float u) {
    return frcp(fminf(flg2(u), -4e-8f));   // negative; nse sign restores +
}

__global__ __launch_bounds__(NT, 5) void reservoir_cell_kernel(
    const float* __restrict__ x_t,         // (B, I)
    const float* __restrict__ h_prev,      // (B, H)
    const float* __restrict__ W_ih_w,      // (H, I)
    const float* __restrict__ W_ih_b,      // (H,)
    const float* __restrict__ W_hh,        // (H, H)
    const float* __restrict__ hh_mask,     // (H, H)
    const float* __restrict__ temperature, // (1,)
    const float* __restrict__ gumbel,      // (B, H, H) uniform(0,1)
    float* __restrict__ out)               // (B, H)
{
    __shared__ float  s_red[8];
    __shared__ float  s_ic[B_];
    __shared__ __align__(16) float s_u[NS][H_];        // 24 KB TMA ring
    __shared__ float2 s_part[B_][NT/2];                // 16 KB post-shuffle partials
    __shared__ __align__(8) unsigned long long s_mb[NS];

    const int o   = blockIdx.x;
    const int tid = threadIdx.x;
    const int wid = tid >> 5;
    const int lid = tid & 31;

    // ---------- pipeline init + prologue: start the DRAM stream immediately ----------
    if (tid == 0) {
        #pragma unroll
        for (int s = 0; s < NS; s++) mbar_init(s2u(&s_mb[s]), 1);
    }
    __syncthreads();
    const float* grow = gumbel + (size_t)o * H_;       // row o of batch 0
    if (tid == 0) {
        #pragma unroll
        for (int s = 0; s < NS; s++) {
            mbar_expect_tx(s2u(&s_mb[s]), ROW_BYTES);
            bulk_ld(s2u(&s_u[s][0]), grow + (size_t)s * H_ * H_, ROW_BYTES, s2u(&s_mb[s]));
        }
    }

    // ---------- phase 1: row logits (log2 domain), block max, nse[8] ----------
    const float s_l2 = 1.4426950408889634f / fmaxf(temperature[0], 1e-3f);
    const float4* wrow = reinterpret_cast<const float4*>(W_hh    + (size_t)o * H_);
    const float4* mrow = reinterpret_cast<const float4*>(hh_mask + (size_t)o * H_);
    float4 wa = wrow[tid], wb = wrow[tid + NT];
    float4 ma = mrow[tid], mb = mrow[tid + NT];
    float e[8];
    e[0] = wa.x*ma.x*s_l2; e[1] = wa.y*ma.y*s_l2; e[2] = wa.z*ma.z*s_l2; e[3] = wa.w*ma.w*s_l2;
    e[4] = wb.x*mb.x*s_l2; e[5] = wb.y*mb.y*s_l2; e[6] = wb.z*mb.z*s_l2; e[7] = wb.w*mb.w*s_l2;

    float m = e[0];
    #pragma unroll
    for (int j = 1; j < 8; j++) m = fmaxf(m, e[j]);
    #pragma unroll
    for (int s = 16; s; s >>= 1) m = fmaxf(m, __shfl_xor_sync(0xffffffffu, m, s));
    if (lid == 0) s_red[wid] = m;
    __syncthreads();
    m = s_red[0];
    #pragma unroll
    for (int j = 1; j < 8; j++) m = fmaxf(m, s_red[j]);

    float nse[8];
    #pragma unroll
    for (int j = 0; j < 8; j++) nse[j] = -1.4426950408889634f * fex2(e[j] - m);

    // ---------- phase 3: consume TMA ring; fused online softmax-dot ----------
    const float4* hp  = reinterpret_cast<const float4*>(h_prev) + tid;
    const float4* su4 = reinterpret_cast<const float4*>(&s_u[0][0]);   // NS*512 float4

    #pragma unroll 1
    for (int b = 0; b < B_; b++) {
        const int q    = b / 3;                // (mul-shift)
        const int slot = b - 3 * q;
        mbar_wait(s2u(&s_mb[slot]), q & 1);

        const float4 ua = su4[slot * (H_/4) + tid];
        const float4 ub = su4[slot * (H_/4) + tid + NT];
        const float4 ha = __ldg(hp);
        const float4 hb = __ldg(hp + NT);

        float n0 = 0.f, d0 = 0.f, n1 = 0.f, d1 = 0.f;
        float w;
        w = nse[0] * gwr(ua.x); n0 = fmaf(w, ha.x, n0); d0 += w;
        w = nse[1] * gwr(ua.y); n1 = fmaf(w, ha.y, n1); d1 += w;
        w = nse[2] * gwr(ua.z); n0 = fmaf(w, ha.z, n0); d0 += w;
        w = nse[3] * gwr(ua.w); n1 = fmaf(w, ha.w, n1); d1 += w;
        w = nse[4] * gwr(ub.x); n0 = fmaf(w, hb.x, n0); d0 += w;
        w = nse[5] * gwr(ub.y); n1 = fmaf(w, hb.y, n1); d1 += w;
        w = nse[6] * gwr(ub.z); n0 = fmaf(w, hb.z, n0); d0 += w;
        w = nse[7] * gwr(ub.w); n1 = fmaf(w, hb.w, n1); d1 += w;

        float ns = n0 + n1, ds = d0 + d1;
        ns += __shfl_xor_sync(0xffffffffu, ns, 16);
        ds += __shfl_xor_sync(0xffffffffu, ds, 16);
        if (lid < 16) s_part[b][wid * 16 + lid] = make_float2(ns, ds);

        __syncthreads();                       // all warps done with this slot
        if (tid == 0 && b + NS < B_) {
            fence_async();
            mbar_expect_tx(s2u(&s_mb[slot]), ROW_BYTES);
            bulk_ld(s2u(&s_u[slot][0]), grow + (size_t)(b + NS) * H_ * H_,
                    ROW_BYTES, s2u(&s_mb[slot]));
        }
        hp += H_ / 4;
    }

    // ---------- phase 2: input contribution; warp w -> batches w and w+8 ----------
    {
        const float4* wr = reinterpret_cast<const float4*>(W_ih_w + (size_t)o * I_);
        const float4* x0 = reinterpret_cast<const float4*>(x_t + (size_t)wid * I_);
        const float4* x1 = reinterpret_cast<const float4*>(x_t + (size_t)(wid + 8) * I_);
        float a0 = 0.f, a1 = 0.f;
        #pragma unroll
        for (int k = lid; k < I_ / 4; k += 32) {
            float4 wv = wr[k];
            float4 v0 = x0[k];
            float4 v1 = x1[k];
            a0 = fmaf(wv.x, v0.x, a0); a0 = fmaf(wv.y, v0.y, a0);
            a0 = fmaf(wv.z, v0.z, a0); a0 = fmaf(wv.w, v0.w, a0);
            a1 = fmaf(wv.x, v1.x, a1); a1 = fmaf(wv.y, v1.y, a1);
            a1 = fmaf(wv.z, v1.z, a1); a1 = fmaf(wv.w, v1.w, a1);
        }
        #pragma unroll
        for (int s = 16; s; s >>= 1) {
            a0 += __shfl_xor_sync(0xffffffffu, a0, s);
            a1 += __shfl_xor_sync(0xffffffffu, a1, s);
        }
        if (lid == 0) {
            float bias = W_ih_b[o];
            s_ic[wid]     = a0 + bias;
            s_ic[wid + 8] = a1 + bias;
        }
    }
    __syncthreads();

    // ---------- phase 4: final reduction; warp w -> batches 2w, 2w+1 ----------
    #pragma unroll
    for (int k = 0; k < 2; k++) {
        const int b = 2 * wid + k;
        const float4* row = reinterpret_cast<const float4*>(&s_part[b][0]);  // 64 float4
        float4 p0 = row[lid], p1 = row[lid + 32];
        float ns = (p0.x + p0.z) + (p1.x + p1.z);
        float ds = (p0.y + p0.w) + (p1.y + p1.w);
        #pragma unroll
        for (int s = 16; s; s >>= 1) {
            ns += __shfl_xor_sync(0xffffffffu, ns, s);
            ds += __shfl_xor_sync(0xffffffffu, ds, s);
        }
        if (lid == 0) out[(size_t)b * H_ + o] = tanhf(s_ic[b] + ns / ds);
    }
}

extern "C" void kernel_launch(void* const* d_in, const int* in_sizes, int n_in,
                              void* d_out, int out_size) {
    const float* x_t         = (const float*)d_in[0];
    const float* h_prev      = (const float*)d_in[1];
    const float* W_ih_w      = (const float*)d_in[2];
    const float* W_ih_b      = (const float*)d_in[3];
    const float* W_hh        = (const float*)d_in[4];
    const float* hh_mask     = (const float*)d_in[5];
    const float* temperature = (const float*)d_in[6];
    const float* gumbel      = (const float*)d_in[7];
    float* out = (float*)d_out;

    reservoir_cell_kernel<<<H_, NT>>>(x_t, h_prev, W_ih_w, W_ih_b, W_hh, hh_mask,
                                      temperature, gumbel, out);
}

// round 11
// speedup vs baseline: 1.1850x; 1.1850x over previous
#include <cuda_runtime.h>

static constexpr int B_  = 16;
static constexpr int H_  = 2048;
static constexpr int I_  = 1024;
static constexpr int NT  = 256;   // 8 warps; warp w owns batches 2w, 2w+1

__device__ __forceinline__ float flg2(float x){ float r; asm("lg2.approx.f32 %0,%1;" : "=f"(r) : "f"(x)); return r; }
__device__ __forceinline__ float frcp(float x){ float r; asm("rcp.approx.f32 %0,%1;" : "=f"(r) : "f"(x)); return r; }
__device__ __forceinline__ float fex2(float x){ float r; asm("ex2.approx.f32 %0,%1;" : "=f"(r) : "f"(x)); return r; }

// w = se / (-ln u) = (-se*log2e) * rcp(lg2(u)).
// Clamp lg2(u) <= -4e-8: lg2.approx's 2^-22 abs error can flip sign near u=1;
// the clamped weight is huge -> dominates num AND den -> output -> h of that
// element, the true u->1 limit. u=0 -> lg2=-inf -> rcp=-0 -> w=+0 (negligible).
__device__ __forceinline__ float gwr(float u) {
    return frcp(fminf(flg2(u), -4e-8f));   // negative; nse sign restores +
}

__global__ __launch_bounds__(NT, 5) void reservoir_cell_kernel(
    const float* __restrict__ x_t,         // (B, I)
    const float* __restrict__ h_prev,      // (B, H)
    const float* __restrict__ W_ih_w,      // (H, I)
    const float* __restrict__ W_ih_b,      // (H,)
    const float* __restrict__ W_hh,        // (H, H)
    const float* __restrict__ hh_mask,     // (H, H)
    const float* __restrict__ temperature, // (1,)
    const float* __restrict__ gumbel,      // (B, H, H) uniform(0,1)
    float* __restrict__ out)               // (B, H)
{
    __shared__ float s_red[8];
    __shared__ __align__(16) float s_nse[H_];   // 8 KB: per-column -se*log2e

    const int o   = blockIdx.x;
    const int tid = threadIdx.x;
    const int wid = tid >> 5;
    const int lid = tid & 31;

    // logits scale folded with log2(e): phase 1 works directly in log2 domain
    const float s_l2 = 1.4426950408889634f / fmaxf(temperature[0], 1e-3f);

    // ---------- phase 1: row logits, block max, nse -> smem ----------
    const float4* wrow = reinterpret_cast<const float4*>(W_hh    + (size_t)o * H_);
    const float4* mrow = reinterpret_cast<const float4*>(hh_mask + (size_t)o * H_);
    float4 wa = wrow[tid], wb = wrow[tid + NT];
    float4 ma = mrow[tid], mb = mrow[tid + NT];
    float e[8];
    e[0] = wa.x*ma.x*s_l2; e[1] = wa.y*ma.y*s_l2; e[2] = wa.z*ma.z*s_l2; e[3] = wa.w*ma.w*s_l2;
    e[4] = wb.x*mb.x*s_l2; e[5] = wb.y*mb.y*s_l2; e[6] = wb.z*mb.z*s_l2; e[7] = wb.w*mb.w*s_l2;

    float m = e[0];
    #pragma unroll
    for (int j = 1; j < 8; j++) m = fmaxf(m, e[j]);
    #pragma unroll
    for (int s = 16; s; s >>= 1) m = fmaxf(m, __shfl_xor_sync(0xffffffffu, m, s));
    if (lid == 0) s_red[wid] = m;
    __syncthreads();
    m = s_red[0];
    #pragma unroll
    for (int j = 1; j < 8; j++) m = fmaxf(m, s_red[j]);

    const float NL2E = -1.4426950408889634f;
    float4* snse4 = reinterpret_cast<float4*>(s_nse);
    snse4[tid]      = make_float4(NL2E*fex2(e[0]-m), NL2E*fex2(e[1]-m),
                                  NL2E*fex2(e[2]-m), NL2E*fex2(e[3]-m));
    snse4[tid + NT] = make_float4(NL2E*fex2(e[4]-m), NL2E*fex2(e[5]-m),
                                  NL2E*fex2(e[6]-m), NL2E*fex2(e[7]-m));
    __syncthreads();   // the ONLY block-wide sync before the stream

    // ---------- phase 3: warp w streams batches 2w and 2w+1, fused ----------
    // Each warp is fully independent: no smem partials, no block syncs.
    const int b0 = 2 * wid;
    const float4* uA = reinterpret_cast<const float4*>(gumbel + ((size_t)b0       * H_ + o) * H_) + lid;
    const float4* uB = reinterpret_cast<const float4*>(gumbel + ((size_t)(b0 + 1) * H_ + o) * H_) + lid;
    const float4* hA = reinterpret_cast<const float4*>(h_prev + (size_t)b0       * H_) + lid;
    const float4* hB = reinterpret_cast<const float4*>(h_prev + (size_t)(b0 + 1) * H_) + lid;
    const float4* sn = reinterpret_cast<const float4*>(s_nse) + lid;

    float n0 = 0.f, d0 = 0.f, n1 = 0.f, d1 = 0.f;

    #pragma unroll 2
    for (int g = 0; g < 16; g++) {           // 16 column-groups of 128 floats
        const float4 ua = __ldcs(uA);
        const float4 ub = __ldcs(uB);
        const float4 ha = __ldg(hA);
        const float4 hb = __ldg(hB);
        const float4 sv = *sn;

        float w;
        w = sv.x * gwr(ua.x); n0 = fmaf(w, ha.x, n0); d0 += w;
        w = sv.y * gwr(ua.y); n0 = fmaf(w, ha.y, n0); d0 += w;
        w = sv.z * gwr(ua.z); n0 = fmaf(w, ha.z, n0); d0 += w;
        w = sv.w * gwr(ua.w); n0 = fmaf(w, ha.w, n0); d0 += w;
        w = sv.x * gwr(ub.x); n1 = fmaf(w, hb.x, n1); d1 += w;
        w = sv.y * gwr(ub.y); n1 = fmaf(w, hb.y, n1); d1 += w;
        w = sv.z * gwr(ub.z); n1 = fmaf(w, hb.z, n1); d1 += w;
        w = sv.w * gwr(ub.w); n1 = fmaf(w, hb.w, n1); d1 += w;

        uA += 32; uB += 32; hA += 32; hB += 32; sn += 32;
    }

    // one-time intra-warp reduction (warps fully independent)
    #pragma unroll
    for (int s = 16; s; s >>= 1) {
        n0 += __shfl_xor_sync(0xffffffffu, n0, s);
        d0 += __shfl_xor_sync(0xffffffffu, d0, s);
        n1 += __shfl_xor_sync(0xffffffffu, n1, s);
        d1 += __shfl_xor_sync(0xffffffffu, d1, s);
    }

    // ---------- phase 2: input contribution for batches b0, b0+1 ----------
    {
        const float4* wr = reinterpret_cast<const float4*>(W_ih_w + (size_t)o * I_);
        const float4* x0 = reinterpret_cast<const float4*>(x_t + (size_t)b0 * I_);
        const float4* x1 = reinterpret_cast<const float4*>(x_t + (size_t)(b0 + 1) * I_);
        float a0 = 0.f, a1 = 0.f;
        #pragma unroll
        for (int k = lid; k < I_ / 4; k += 32) {
            float4 wv = wr[k];
            float4 v0 = x0[k];
            float4 v1 = x1[k];
            a0 = fmaf(wv.x, v0.x, a0); a0 = fmaf(wv.y, v0.y, a0);
            a0 = fmaf(wv.z, v0.z, a0); a0 = fmaf(wv.w, v0.w, a0);
            a1 = fmaf(wv.x, v1.x, a1); a1 = fmaf(wv.y, v1.y, a1);
            a1 = fmaf(wv.z, v1.z, a1); a1 = fmaf(wv.w, v1.w, a1);
        }
        #pragma unroll
        for (int s = 16; s; s >>= 1) {
            a0 += __shfl_xor_sync(0xffffffffu, a0, s);
            a1 += __shfl_xor_sync(0xffffffffu, a1, s);
        }
        if (lid == 0) {
            const float bias = W_ih_b[o];
            out[(size_t)b0 * H_ + o]       = tanhf(a0 + bias + n0 / d0);
            out[(size_t)(b0 + 1) * H_ + o] = tanhf(a1 + bias + n1 / d1);
        }
    }
}

extern "C" void kernel_launch(void* const* d_in, const int* in_sizes, int n_in,
                              void* d_out, int out_size) {
    const float* x_t         = (const float*)d_in[0];
    const float* h_prev      = (const float*)d_in[1];
    const float* W_ih_w      = (const float*)d_in[2];
    const float* W_ih_b      = (const float*)d_in[3];
    const float* W_hh        = (const float*)d_in[4];
    const float* hh_mask     = (const float*)d_in[5];
    const float* temperature = (const float*)d_in[6];
    const float* gumbel      = (const float*)d_in[7];
    float* out = (float*)d_out;

    reservoir_cell_kernel<<<H_, NT>>>(x_t, h_prev, W_ih_w, W_ih_b, W_hh, hh_mask,
                                      temperature, gumbel, out);
}

// round 12
// speedup vs baseline: 1.2125x; 1.0232x over previous
#include <cuda_runtime.h>

static constexpr int B_  = 16;
static constexpr int H_  = 2048;
static constexpr int I_  = 1024;
static constexpr int NT  = 256;   // 8 warps; each thread owns 8 columns

__device__ __forceinline__ float flg2(float x){ float r; asm("lg2.approx.f32 %0,%1;" : "=f"(r) : "f"(x)); return r; }
__device__ __forceinline__ float frcp(float x){ float r; asm("rcp.approx.f32 %0,%1;" : "=f"(r) : "f"(x)); return r; }
__device__ __forceinline__ float fex2(float x){ float r; asm("ex2.approx.f32 %0,%1;" : "=f"(r) : "f"(x)); return r; }

// Clamped lg2: l in [-33.2193, -4e-8].
//  upper: lg2.approx abs err 2^-22 can flip sign near u=1 -> clamp keeps the
//         weight huge-positive (dominates num AND den -> true u->1 limit).
//  lower: -33.2193 = lg2(1e-10), so u=0 maps to t = -ln(1e-10) = 23.03 --
//         EXACTLY the reference's u=0 weight -- and keeps the 4-way product
//         finite (no inf poisoning the shared-rcp group).
__device__ __forceinline__ float clg2(float u) {
    return fmaxf(fminf(flg2(u), -4e-8f), -33.2193f);
}

__global__ __launch_bounds__(NT, 5) void reservoir_cell_kernel(
    const float* __restrict__ x_t,         // (B, I)
    const float* __restrict__ h_prev,      // (B, H)
    const float* __restrict__ W_ih_w,      // (H, I)
    const float* __restrict__ W_ih_b,      // (H,)
    const float* __restrict__ W_hh,        // (H, H)
    const float* __restrict__ hh_mask,     // (H, H)
    const float* __restrict__ temperature, // (1,)
    const float* __restrict__ gumbel,      // (B, H, H) uniform(0,1)
    float* __restrict__ out)               // (B, H)
{
    __shared__ float  s_red[8];
    __shared__ float  s_ic[B_];
    __shared__ float2 s_part[B_][NT];      // 32 KB per-thread (num,den) partials

    const int o   = blockIdx.x;
    const int tid = threadIdx.x;
    const int wid = tid >> 5;
    const int lid = tid & 31;

    // logits scale folded with log2(e): phase 1 works directly in log2 domain
    const float s_l2 = 1.4426950408889634f / fmaxf(temperature[0], 1e-3f);

    // ---------- phase 1: row logits (log2 domain), block max, nse[8] in regs ----------
    const float4* wrow = reinterpret_cast<const float4*>(W_hh    + (size_t)o * H_);
    const float4* mrow = reinterpret_cast<const float4*>(hh_mask + (size_t)o * H_);
    float4 wa = wrow[tid], wb = wrow[tid + NT];
    float4 ma = mrow[tid], mb = mrow[tid + NT];
    float e[8];
    e[0] = wa.x*ma.x*s_l2; e[1] = wa.y*ma.y*s_l2; e[2] = wa.z*ma.z*s_l2; e[3] = wa.w*ma.w*s_l2;
    e[4] = wb.x*mb.x*s_l2; e[5] = wb.y*mb.y*s_l2; e[6] = wb.z*mb.z*s_l2; e[7] = wb.w*mb.w*s_l2;

    float m = e[0];
    #pragma unroll
    for (int j = 1; j < 8; j++) m = fmaxf(m, e[j]);
    #pragma unroll
    for (int s = 16; s; s >>= 1) m = fmaxf(m, __shfl_xor_sync(0xffffffffu, m, s));
    if (lid == 0) s_red[wid] = m;
    __syncthreads();
    m = s_red[0];
    #pragma unroll
    for (int j = 1; j < 8; j++) m = fmaxf(m, s_red[j]);

    // nse = -se * log2(e): sign + 1/ln2 folded so w = nse * (1/lg2(u))
    float nse[8];
    #pragma unroll
    for (int j = 0; j < 8; j++) nse[j] = -1.4426950408889634f * fex2(e[j] - m);

    // ---------- phase 3: stream gumbel; rolling depth-1 prefetch; shared-rcp groups ----------
    const size_t bstride4 = (size_t)H_ * H_ / 4;           // float4 stride between batches
    const float4* gu = reinterpret_cast<const float4*>(gumbel + (size_t)o * H_) + tid;
    const float4* pf = gu + bstride4;                      // prefetch: batch b+1
    const float4* hp = reinterpret_cast<const float4*>(h_prev) + tid;
    float2* sp = &s_part[0][tid];

    float4 ua = __ldcs(gu);
    float4 ub = __ldcs(gu + NT);

    #pragma unroll 4
    for (int b = 0; b < B_; b++) {
        const float4 na  = __ldcs(pf);                     // re-reads batch 15 on last iter
        const float4 nbv = __ldcs(pf + NT);
        const float4 ha  = __ldg(hp);
        const float4 hb  = __ldg(hp + NT);

        float num = 0.f, den = 0.f;

        // group A: one rcp serves four reciprocals of lg2 values
        {
            float l0 = clg2(ua.x), l1 = clg2(ua.y), l2 = clg2(ua.z), l3 = clg2(ua.w);
            float p01 = l0 * l1, p23 = l2 * l3;
            float r   = frcp(p01 * p23);                   // 1/(l0 l1 l2 l3)
            float r01 = r * p23, r23 = r * p01;            // 1/(l0 l1), 1/(l2 l3)
            float w;
            w = nse[0] * (r01 * l1); num = fmaf(w, ha.x, num); den += w;
            w = nse[1] * (r01 * l0); num = fmaf(w, ha.y, num); den += w;
            w = nse[2] * (r23 * l3); num = fmaf(w, ha.z, num); den += w;
            w = nse[3] * (r23 * l2); num = fmaf(w, ha.w, num); den += w;
        }
        // group B
        {
            float l0 = clg2(ub.x), l1 = clg2(ub.y), l2 = clg2(ub.z), l3 = clg2(ub.w);
            float p01 = l0 * l1, p23 = l2 * l3;
            float r   = frcp(p01 * p23);
            float r01 = r * p23, r23 = r * p01;
            float w;
            w = nse[4] * (r01 * l1); num = fmaf(w, hb.x, num); den += w;
            w = nse[5] * (r01 * l0); num = fmaf(w, hb.y, num); den += w;
            w = nse[6] * (r23 * l3); num = fmaf(w, hb.z, num); den += w;
            w = nse[7] * (r23 * l2); num = fmaf(w, hb.w, num); den += w;
        }

        *sp = make_float2(num, den);                       // contiguous 256B/warp

        ua = na; ub = nbv;
        pf += (b < B_ - 2) ? bstride4 : 0;                 // clamp: stay in-bounds
        hp += H_ / 4;
        sp += NT;
    }

    // ---------- phase 2: input contribution; warp w -> batches w and w+8 ----------
    {
        const float4* wr = reinterpret_cast<const float4*>(W_ih_w + (size_t)o * I_);
        const float4* x0 = reinterpret_cast<const float4*>(x_t + (size_t)wid * I_);
        const float4* x1 = reinterpret_cast<const float4*>(x_t + (size_t)(wid + 8) * I_);
        float a0 = 0.f, a1 = 0.f;
        #pragma unroll
        for (int k = lid; k < I_ / 4; k += 32) {
            float4 wv = wr[k];
            float4 v0 = x0[k];
            float4 v1 = x1[k];
            a0 = fmaf(wv.x, v0.x, a0); a0 = fmaf(wv.y, v0.y, a0);
            a0 = fmaf(wv.z, v0.z, a0); a0 = fmaf(wv.w, v0.w, a0);
            a1 = fmaf(wv.x, v1.x, a1); a1 = fmaf(wv.y, v1.y, a1);
            a1 = fmaf(wv.z, v1.z, a1); a1 = fmaf(wv.w, v1.w, a1);
        }
        #pragma unroll
        for (int s = 16; s; s >>= 1) {
            a0 += __shfl_xor_sync(0xffffffffu, a0, s);
            a1 += __shfl_xor_sync(0xffffffffu, a1, s);
        }
        if (lid == 0) {
            float bias = W_ih_b[o];
            s_ic[wid]     = a0 + bias;
            s_ic[wid + 8] = a1 + bias;
        }
    }
    __syncthreads();

    // ---------- phase 4: one-time reduction; warp w -> batches 2w, 2w+1 ----------
    #pragma unroll
    for (int k = 0; k < 2; k++) {
        const int b = 2 * wid + k;
        const float4* row = reinterpret_cast<const float4*>(&s_part[b][0]);   // 128 float4
        float4 p0 = row[lid], p1 = row[lid + 32], p2 = row[lid + 64], p3 = row[lid + 96];
        float ns = (p0.x + p1.x) + (p2.x + p3.x) + (p0.z + p1.z) + (p2.z + p3.z);
        float ds = (p0.y + p1.y) + (p2.y + p3.y) + (p0.w + p1.w) + (p2.w + p3.w);
        #pragma unroll
        for (int s = 16; s; s >>= 1) {
            ns += __shfl_xor_sync(0xffffffffu, ns, s);
            ds += __shfl_xor_sync(0xffffffffu, ds, s);
        }
        if (lid == 0) out[(size_t)b * H_ + o] = tanhf(s_ic[b] + ns / ds);
    }
}

extern "C" void kernel_launch(void* const* d_in, const int* in_sizes, int n_in,
                              void* d_out, int out_size) {
    const float* x_t         = (const float*)d_in[0];
    const float* h_prev      = (const float*)d_in[1];
    const float* W_ih_w      = (const float*)d_in[2];
    const float* W_ih_b      = (const float*)d_in[3];
    const float* W_hh        = (const float*)d_in[4];
    const float* hh_mask     = (const float*)d_in[5];
    const float* temperature = (const float*)d_in[6];
    const float* gumbel      = (const float*)d_in[7];
    float* out = (float*)d_out;

    reservoir_cell_kernel<<<H_, NT>>>(x_t, h_prev, W_ih_w, W_ih_b, W_hh, hh_mask,
                                      temperature, gumbel, out);
}